// round 16
// baseline (speedup 1.0000x reference)
#include <cuda_runtime.h>
#include <cuda_bf16.h>
#include <cstdint>
#include <math.h>

#define N_ROIS 128
#define BEV_H 188
#define BEV_W 188
#define BEV_C 256
#define THREADS 256
#define FULL 0xFFFFFFFFu
#define MAXN 262144

// per-point params (static scratch; no runtime allocation)
// g_pack: x0 | x1<<8 | y0<<16 | y1<<24 ; == -1 -> masked-out (zero row)
__device__ int    g_pack[MAXN];
__device__ float4 g_wt[MAXN];

// ================= kernel 1: thread-per-point argmin + params =================
__global__ void __launch_bounds__(THREADS)
k_phase1(const float* __restrict__ points,
         const float* __restrict__ rois, int n)
{
    __shared__ float4 s_roi[N_ROIS];   // (cx, cy, cz, ||dims/2||+2.4)

    if (threadIdx.x < N_ROIS) {
        const float* rp = rois + threadIdx.x * 7;
        const float hl = rp[3] * 0.5f;
        const float hw = rp[4] * 0.5f;
        const float hh = rp[5] * 0.5f;
        const float rad = sqrtf(hl * hl + hw * hw + hh * hh) + 2.4f;
        s_roi[threadIdx.x] = make_float4(rp[0], rp[1], rp[2], rad);
    }
    __syncthreads();

    const int p = blockIdx.x * THREADS + threadIdx.x;
    if (p >= n) return;

    const float px = points[p * 3 + 0];
    const float py = points[p * 3 + 1];
    const float pz = points[p * 3 + 2];

    float best = INFINITY;
    int bidx = 0;
    #pragma unroll 4
    for (int r = 0; r < N_ROIS; r++) {
        const float4 q = s_roi[r];     // warp-broadcast LDS.128
        const float dx = px - q.x;
        const float dy = py - q.y;
        const float dz = pz - q.z;
        const float d2 = dx * dx + dy * dy + dz * dz;
        if (d2 < best) { best = d2; bidx = r; }   // '<' -> first occurrence
    }
    const bool mask = sqrtf(best) < s_roi[bidx].w;

    if (!mask) {
        g_pack[p] = -1;
        return;
    }

    // bit-faithful coords: two fp32 divides, floor, clamp
    const float xi = (px - 0.0f)   / 0.05f / 8.0f;
    const float yi = (py - -40.0f) / 0.05f / 8.0f;
    const int xf = (int)floorf(xi);
    const int yf = (int)floorf(yi);
    const int x0 = min(max(xf,     0), BEV_W - 1);
    const int x1 = min(max(xf + 1, 0), BEV_W - 1);
    const int y0 = min(max(yf,     0), BEV_H - 1);
    const int y1 = min(max(yf + 1, 0), BEV_H - 1);

    const float x0f = (float)x0, x1f = (float)x1;
    const float y0f = (float)y0, y1f = (float)y1;
    float4 wt;
    wt.x = (x1f - xi) * (y1f - yi);   // wa
    wt.y = (x1f - xi) * (yi - y0f);   // wb
    wt.z = (xi - x0f) * (y1f - yi);   // wc
    wt.w = (xi - x0f) * (yi - y0f);   // wd

    g_wt[p]   = wt;
    // coords <= 187 fit in a byte each; all-ones (-1) is unreachable (needs 255s)
    g_pack[p] = x0 | (x1 << 8) | (y0 << 16) | (y1 << 24);
}

// ================= kernel 2: fused gather (warp/pt) + zero (thread/chunk) =====
// blocks [0, GB)        : gather path, warp-per-point
// blocks [GB, GB + ZB)  : zero path, thread-per-float4-chunk (64 chunks/row)
__global__ void __launch_bounds__(THREADS)
k_phase2(const float* __restrict__ bev, float* __restrict__ out,
         int n, int GB)
{
    if (blockIdx.x >= GB) {
        // ---------------- zero path: 2-instruction chain ----------------
        const long long i = (long long)(blockIdx.x - GB) * THREADS + threadIdx.x;
        const int p = (int)(i >> 6);          // 64 float4-chunks per row
        if (p >= n) return;
        const int pk = g_pack[p];             // 64-thread broadcast, L2-resident
        if (pk != -1) return;                 // not a zero row
        const int c = (int)(i & 63);
        const float4 z = make_float4(0.f, 0.f, 0.f, 0.f);
        __stcs(reinterpret_cast<float4*>(out + (size_t)p * BEV_C) + c, z);
        return;
    }

    // ---------------- gather path: warp-per-point ----------------
    const int lane = threadIdx.x & 31;
    const int p    = blockIdx.x * (THREADS / 32) + (threadIdx.x >> 5);
    if (p >= n) return;

    const int pk = g_pack[p];                 // warp-broadcast 4B load
    if (pk == -1) return;                     // zero row handled by zero path

    const float4 wv = g_wt[p];                // warp-broadcast LDG.128

    const int x0 =  pk        & 255;
    const int x1 = (pk >> 8)  & 255;
    const int y0 = (pk >> 16) & 255;
    const int y1 = (pk >> 24) & 255;

    const float4* A  = reinterpret_cast<const float4*>(bev + ((size_t)y0 * BEV_W + x0) * BEV_C);
    const float4* B  = reinterpret_cast<const float4*>(bev + ((size_t)y1 * BEV_W + x0) * BEV_C);
    const float4* Cc = reinterpret_cast<const float4*>(bev + ((size_t)y0 * BEV_W + x1) * BEV_C);
    const float4* D  = reinterpret_cast<const float4*>(bev + ((size_t)y1 * BEV_W + x1) * BEV_C);

    // all 8 corner loads issued before FMAs
    const float4 a0 = __ldcg(A  + lane);
    const float4 b0 = __ldcg(B  + lane);
    const float4 c0 = __ldcg(Cc + lane);
    const float4 d0 = __ldcg(D  + lane);
    const float4 a1 = __ldcg(A  + lane + 32);
    const float4 b1 = __ldcg(B  + lane + 32);
    const float4 c1 = __ldcg(Cc + lane + 32);
    const float4 d1 = __ldcg(D  + lane + 32);

    float4 o0, o1;
    o0.x = a0.x * wv.x + b0.x * wv.y + c0.x * wv.z + d0.x * wv.w;
    o0.y = a0.y * wv.x + b0.y * wv.y + c0.y * wv.z + d0.y * wv.w;
    o0.z = a0.z * wv.x + b0.z * wv.y + c0.z * wv.z + d0.z * wv.w;
    o0.w = a0.w * wv.x + b0.w * wv.y + c0.w * wv.z + d0.w * wv.w;
    o1.x = a1.x * wv.x + b1.x * wv.y + c1.x * wv.z + d1.x * wv.w;
    o1.y = a1.y * wv.x + b1.y * wv.y + c1.y * wv.z + d1.y * wv.w;
    o1.z = a1.z * wv.x + b1.z * wv.y + c1.z * wv.z + d1.z * wv.w;
    o1.w = a1.w * wv.x + b1.w * wv.y + c1.w * wv.z + d1.w * wv.w;

    float4* op = reinterpret_cast<float4*>(out + (size_t)p * BEV_C);
    __stcs(op + lane,      o0);
    __stcs(op + lane + 32, o1);
}

extern "C" void kernel_launch(void* const* d_in, const int* in_sizes, int n_in,
                              void* d_out, int out_size)
{
    const float* points = (const float*)d_in[0];
    const float* rois   = (const float*)d_in[1];
    const float* bev    = (const float*)d_in[2];
    float* out = (float*)d_out;

    const int n = in_sizes[0] / 3;   // n <= MAXN

    k_phase1<<<(n + THREADS - 1) / THREADS, THREADS>>>(points, rois, n);

    const int GB = (n + (THREADS / 32) - 1) / (THREADS / 32);   // gather blocks
    const long long chunks = (long long)n * 64;                 // zero chunks
    const int ZB = (int)((chunks + THREADS - 1) / THREADS);     // zero blocks
    k_phase2<<<GB + ZB, THREADS>>>(bev, out, n, GB);
}

// round 17
// speedup vs baseline: 1.3258x; 1.3258x over previous
#include <cuda_runtime.h>
#include <cuda_bf16.h>
#include <cstdint>
#include <math.h>

#define N_ROIS 128
#define BEV_H 188
#define BEV_W 188
#define BEV_C 256
#define THREADS 256
#define FULL 0xFFFFFFFFu
#define MAXN 262144

// per-point params (static scratch; no runtime allocation)
// g_pack: x0 | x1<<8 | y0<<16 | y1<<24 ; == -1 -> masked-out (zero row)
__device__ int    g_pack[MAXN];
__device__ float4 g_wt[MAXN];

// ================= kernel 1: thread-per-point argmin + params =================
__global__ void __launch_bounds__(THREADS)
k_phase1(const float* __restrict__ points,
         const float* __restrict__ rois, int n)
{
    __shared__ float4 s_roi[N_ROIS];   // (cx, cy, cz, ||dims/2||+2.4)

    if (threadIdx.x < N_ROIS) {
        const float* rp = rois + threadIdx.x * 7;
        const float hl = rp[3] * 0.5f;
        const float hw = rp[4] * 0.5f;
        const float hh = rp[5] * 0.5f;
        const float rad = sqrtf(hl * hl + hw * hw + hh * hh) + 2.4f;
        s_roi[threadIdx.x] = make_float4(rp[0], rp[1], rp[2], rad);
    }
    __syncthreads();

    const int p = blockIdx.x * THREADS + threadIdx.x;
    if (p >= n) return;

    const float px = points[p * 3 + 0];
    const float py = points[p * 3 + 1];
    const float pz = points[p * 3 + 2];

    float best = INFINITY;
    int bidx = 0;
    #pragma unroll 4
    for (int r = 0; r < N_ROIS; r++) {
        const float4 q = s_roi[r];     // warp-broadcast LDS.128
        const float dx = px - q.x;
        const float dy = py - q.y;
        const float dz = pz - q.z;
        const float d2 = dx * dx + dy * dy + dz * dz;
        if (d2 < best) { best = d2; bidx = r; }   // '<' -> first occurrence
    }
    const bool mask = sqrtf(best) < s_roi[bidx].w;

    if (!mask) {
        g_pack[p] = -1;
        return;
    }

    // bit-faithful coords: two fp32 divides, floor, clamp
    const float xi = (px - 0.0f)   / 0.05f / 8.0f;
    const float yi = (py - -40.0f) / 0.05f / 8.0f;
    const int xf = (int)floorf(xi);
    const int yf = (int)floorf(yi);
    const int x0 = min(max(xf,     0), BEV_W - 1);
    const int x1 = min(max(xf + 1, 0), BEV_W - 1);
    const int y0 = min(max(yf,     0), BEV_H - 1);
    const int y1 = min(max(yf + 1, 0), BEV_H - 1);

    const float x0f = (float)x0, x1f = (float)x1;
    const float y0f = (float)y0, y1f = (float)y1;
    float4 wt;
    wt.x = (x1f - xi) * (y1f - yi);   // wa
    wt.y = (x1f - xi) * (yi - y0f);   // wb
    wt.z = (xi - x0f) * (y1f - yi);   // wc
    wt.w = (xi - x0f) * (yi - y0f);   // wd

    g_wt[p]   = wt;
    // coords <= 187 fit in a byte; -1 (all-ones) is unreachable
    g_pack[p] = x0 | (x1 << 8) | (y0 << 16) | (y1 << 24);
}

// helper: corner-row pointers from packed coords
__device__ __forceinline__ void corners(int pk, const float* bev,
                                        const float4*& A, const float4*& B,
                                        const float4*& C, const float4*& D)
{
    const int x0 =  pk        & 255;
    const int x1 = (pk >> 8)  & 255;
    const int y0 = (pk >> 16) & 255;
    const int y1 = (pk >> 24) & 255;
    A = reinterpret_cast<const float4*>(bev + ((size_t)y0 * BEV_W + x0) * BEV_C);
    B = reinterpret_cast<const float4*>(bev + ((size_t)y1 * BEV_W + x0) * BEV_C);
    C = reinterpret_cast<const float4*>(bev + ((size_t)y0 * BEV_W + x1) * BEV_C);
    D = reinterpret_cast<const float4*>(bev + ((size_t)y1 * BEV_W + x1) * BEV_C);
}

// ================= kernel 2: warp-per-2-points, batched MLP=16 =================
__global__ void __launch_bounds__(THREADS)
k_phase2(const float* __restrict__ bev, float* __restrict__ out, int n)
{
    const int lane = threadIdx.x & 31;
    const int wix  = blockIdx.x * (THREADS / 32) + (threadIdx.x >> 5);
    const int pA   = wix * 2;
    const int pB   = pA + 1;
    if (pA >= n) return;
    const bool hasB = pB < n;

    // both packs issued together (independent round trips)
    const int pkA = g_pack[pA];
    const int pkB = hasB ? g_pack[pB] : -1;
    const bool gA = (pkA != -1);
    const bool gB = (pkB != -1);

    // weights (only needed for gather points; issue early, warp-uniform)
    float4 wvA, wvB;
    if (gA) wvA = g_wt[pA];
    if (gB) wvB = g_wt[pB];

    const float4 z = make_float4(0.f, 0.f, 0.f, 0.f);
    float4* opA = reinterpret_cast<float4*>(out + (size_t)pA * BEV_C);
    float4* opB = reinterpret_cast<float4*>(out + (size_t)pB * BEV_C);

    // ---- issue ALL corner loads for both points first (MLP up to 16) ----
    float4 a0, b0, c0, d0, a1, b1, c1, d1;     // point A
    float4 e0, f0, g0, h0, e1, f1, g1, h1;     // point B
    if (gA) {   // warp-uniform branch
        const float4 *A, *B, *C, *D;
        corners(pkA, bev, A, B, C, D);
        a0 = __ldcg(A + lane);       b0 = __ldcg(B + lane);
        c0 = __ldcg(C + lane);       d0 = __ldcg(D + lane);
        a1 = __ldcg(A + lane + 32);  b1 = __ldcg(B + lane + 32);
        c1 = __ldcg(C + lane + 32);  d1 = __ldcg(D + lane + 32);
    }
    if (gB) {   // warp-uniform branch
        const float4 *A, *B, *C, *D;
        corners(pkB, bev, A, B, C, D);
        e0 = __ldcg(A + lane);       f0 = __ldcg(B + lane);
        g0 = __ldcg(C + lane);       h0 = __ldcg(D + lane);
        e1 = __ldcg(A + lane + 32);  f1 = __ldcg(B + lane + 32);
        g1 = __ldcg(C + lane + 32);  h1 = __ldcg(D + lane + 32);
    }

    // ---- zero rows go out while gather loads are in flight ----
    if (!gA) {
        __stcs(opA + lane,      z);
        __stcs(opA + lane + 32, z);
    }
    if (hasB && !gB) {
        __stcs(opB + lane,      z);
        __stcs(opB + lane + 32, z);
    }

    // ---- point A compute + store ----
    if (gA) {
        float4 o0, o1;
        o0.x = a0.x * wvA.x + b0.x * wvA.y + c0.x * wvA.z + d0.x * wvA.w;
        o0.y = a0.y * wvA.x + b0.y * wvA.y + c0.y * wvA.z + d0.y * wvA.w;
        o0.z = a0.z * wvA.x + b0.z * wvA.y + c0.z * wvA.z + d0.z * wvA.w;
        o0.w = a0.w * wvA.x + b0.w * wvA.y + c0.w * wvA.z + d0.w * wvA.w;
        o1.x = a1.x * wvA.x + b1.x * wvA.y + c1.x * wvA.z + d1.x * wvA.w;
        o1.y = a1.y * wvA.x + b1.y * wvA.y + c1.y * wvA.z + d1.y * wvA.w;
        o1.z = a1.z * wvA.x + b1.z * wvA.y + c1.z * wvA.z + d1.z * wvA.w;
        o1.w = a1.w * wvA.x + b1.w * wvA.y + c1.w * wvA.z + d1.w * wvA.w;
        __stcs(opA + lane,      o0);
        __stcs(opA + lane + 32, o1);
    }

    // ---- point B compute + store ----
    if (gB) {
        float4 o0, o1;
        o0.x = e0.x * wvB.x + f0.x * wvB.y + g0.x * wvB.z + h0.x * wvB.w;
        o0.y = e0.y * wvB.x + f0.y * wvB.y + g0.y * wvB.z + h0.y * wvB.w;
        o0.z = e0.z * wvB.x + f0.z * wvB.y + g0.z * wvB.z + h0.z * wvB.w;
        o0.w = e0.w * wvB.x + f0.w * wvB.y + g0.w * wvB.z + h0.w * wvB.w;
        o1.x = e1.x * wvB.x + f1.x * wvB.y + g1.x * wvB.z + h1.x * wvB.w;
        o1.y = e1.y * wvB.x + f1.y * wvB.y + g1.y * wvB.z + h1.y * wvB.w;
        o1.z = e1.z * wvB.x + f1.z * wvB.y + g1.z * wvB.z + h1.z * wvB.w;
        o1.w = e1.w * wvB.x + f1.w * wvB.y + g1.w * wvB.z + h1.w * wvB.w;
        __stcs(opB + lane,      o0);
        __stcs(opB + lane + 32, o1);
    }
}

extern "C" void kernel_launch(void* const* d_in, const int* in_sizes, int n_in,
                              void* d_out, int out_size)
{
    const float* points = (const float*)d_in[0];
    const float* rois   = (const float*)d_in[1];
    const float* bev    = (const float*)d_in[2];
    float* out = (float*)d_out;

    const int n = in_sizes[0] / 3;   // n <= MAXN

    k_phase1<<<(n + THREADS - 1) / THREADS, THREADS>>>(points, rois, n);

    const int nwarps = (n + 1) / 2;                   // one warp per 2 points
    const int blocks = (nwarps + (THREADS / 32) - 1) / (THREADS / 32);
    k_phase2<<<blocks, THREADS>>>(bev, out, n);
}